// round 1
// baseline (speedup 1.0000x reference)
#include <cuda_runtime.h>
#include <cuda_bf16.h>
#include <math.h>

#define CC 256
#define HH 56
#define WW 56
#define PP (HH*WW)        // 3136
#define BB 16
#define NTOT (BB*CC*PP)   // 12845056
#define EPSF 1e-5f

// Scratch (allocation-free contract: __device__ globals)
__device__ float g_mid[NTOT];    // pw1 output
__device__ float g_top[NTOT];    // gated/fused depthwise output
__device__ float g_out2[NTOT];   // pw2+bn+relu output
__device__ float g_sum[BB*CC];   // SE squeeze sums
__device__ float g_se[BB*CC];    // SE sigmoid scales

// ---------------------------------------------------------------------------
// K0: zero the SE accumulators (graph replays -> must re-zero every launch)
__global__ void k_zero() {
    int i = blockIdx.x * blockDim.x + threadIdx.x;
    if (i < BB*CC) g_sum[i] = 0.f;
}

// ---------------------------------------------------------------------------
// K1: pw1 GEMM.  g_mid[b,o,p] = sum_c W[o,c] * x[b,c,p]
// Tile: 128 (o) x 64 (p), K-tile 16, 256 threads, 8x4 per thread.
__global__ __launch_bounds__(256) void k_pw1(const float* __restrict__ X,
                                             const float* __restrict__ W) {
    const int b  = blockIdx.z;
    const int o0 = blockIdx.y * 128;
    const int p0 = blockIdx.x * 64;
    __shared__ float As[16][128];
    __shared__ float Bs[16][64];
    const int tid = threadIdx.x;
    const int tx = tid & 15, ty = tid >> 4;
    const float* Xb = X + (size_t)b * CC * PP;
    float acc[8][4] = {};

    for (int kt = 0; kt < CC; kt += 16) {
        {   // A: weights W[o0+tid/2][kt + (tid&1)*8 .. +7]
            int o  = o0 + (tid >> 1);
            int k4 = (tid & 1) * 8;
            const float4* src = reinterpret_cast<const float4*>(W + o * CC + kt + k4);
            float4 v0 = src[0], v1 = src[1];
            int col = tid >> 1;
            As[k4+0][col] = v0.x; As[k4+1][col] = v0.y;
            As[k4+2][col] = v0.z; As[k4+3][col] = v0.w;
            As[k4+4][col] = v1.x; As[k4+5][col] = v1.y;
            As[k4+6][col] = v1.z; As[k4+7][col] = v1.w;
        }
        {   // B: activations X[b, kt+tid/16, p0 + (tid&15)*4 .. +3]
            int k  = tid >> 4;
            int pp = (tid & 15) * 4;
            float4 v = *reinterpret_cast<const float4*>(Xb + (size_t)(kt + k) * PP + p0 + pp);
            *reinterpret_cast<float4*>(&Bs[k][pp]) = v;
        }
        __syncthreads();
        #pragma unroll
        for (int kk = 0; kk < 16; kk++) {
            float a[8], bb[4];
            *reinterpret_cast<float4*>(a)     = *reinterpret_cast<const float4*>(&As[kk][ty*8]);
            *reinterpret_cast<float4*>(a + 4) = *reinterpret_cast<const float4*>(&As[kk][ty*8+4]);
            *reinterpret_cast<float4*>(bb)    = *reinterpret_cast<const float4*>(&Bs[kk][tx*4]);
            #pragma unroll
            for (int i = 0; i < 8; i++)
                #pragma unroll
                for (int j = 0; j < 4; j++)
                    acc[i][j] = fmaf(a[i], bb[j], acc[i][j]);
        }
        __syncthreads();
    }
    #pragma unroll
    for (int i = 0; i < 8; i++) {
        size_t off = (size_t)(b*CC + o0 + ty*8 + i) * PP + p0 + tx*4;
        *reinterpret_cast<float4*>(&g_mid[off]) =
            make_float4(acc[i][0], acc[i][1], acc[i][2], acc[i][3]);
    }
}

// ---------------------------------------------------------------------------
// K2: fused depthwise branches + BN + ReLU + gate.  One block per (b,c) plane.
__global__ __launch_bounds__(256) void k_dw(
    const float* __restrict__ xy3, const float* __restrict__ xy5,
    const float* __restrict__ bnxy_g, const float* __restrict__ bnxy_b,
    const float* __restrict__ bnxy_m, const float* __restrict__ bnxy_v,
    const float* __restrict__ xz3, const float* __restrict__ xz5,
    const float* __restrict__ bnxz_g, const float* __restrict__ bnxz_b,
    const float* __restrict__ bnxz_m, const float* __restrict__ bnxz_v,
    const float* __restrict__ yz3, const float* __restrict__ yz5,
    const float* __restrict__ bnyz_g, const float* __restrict__ bnyz_b,
    const float* __restrict__ bnyz_m, const float* __restrict__ bnyz_v,
    const float* __restrict__ alpha, const float* __restrict__ beta) {

    const int c = blockIdx.x;
    const int b = blockIdx.y;
    const int tid = threadIdx.x;
    const size_t base = (size_t)(b*CC + c) * PP;

    __shared__ float sp[60*60];     // plane with halo 2
    __shared__ float wk[52];        // packed depthwise weights

    // load haloed plane (zero pad)
    for (int idx = tid; idx < 60*60; idx += 256) {
        int r = idx / 60, cl = idx - r*60;
        int h = r - 2, w = cl - 2;
        float v = 0.f;
        if (h >= 0 && h < HH && w >= 0 && w < WW) v = g_mid[base + h*WW + w];
        sp[idx] = v;
    }
    // pack weights: [0..8]=xy3, [9..33]=xy5, [34..36]=xz3, [37..41]=xz5,
    //               [42..44]=yz3, [45..49]=yz5
    if (tid < 9)       wk[tid] = xy3[c*9  + tid];
    else if (tid < 34) wk[tid] = xy5[c*25 + tid-9];
    else if (tid < 37) wk[tid] = xz3[c*3  + tid-34];
    else if (tid < 42) wk[tid] = xz5[c*5  + tid-37];
    else if (tid < 45) wk[tid] = yz3[c*3  + tid-42];
    else if (tid < 50) wk[tid] = yz5[c*5  + tid-45];
    __syncthreads();

    const float scxy = bnxy_g[c] * rsqrtf(bnxy_v[c] + EPSF);
    const float shxy = bnxy_b[c] - bnxy_m[c] * scxy;
    const float scxz = bnxz_g[c] * rsqrtf(bnxz_v[c] + EPSF);
    const float shxz = bnxz_b[c] - bnxz_m[c] * scxz;
    const float scyz = bnyz_g[c] * rsqrtf(bnyz_v[c] + EPSF);
    const float shyz = bnyz_b[c] - bnyz_m[c] * scyz;
    const float al = alpha[c], be = beta[c];

    for (int p = tid; p < PP; p += 256) {
        int hh = p / WW;
        int ww = p - hh*WW;
        float win[25];
        #pragma unroll
        for (int i = 0; i < 5; i++)
            #pragma unroll
            for (int j = 0; j < 5; j++)
                win[i*5+j] = sp[(hh+i)*60 + ww + j];

        float sxy = 0.f, sxz = 0.f, syz = 0.f;
        #pragma unroll
        for (int i = 0; i < 5; i++)
            #pragma unroll
            for (int j = 0; j < 5; j++)
                sxy = fmaf(win[i*5+j], wk[9 + i*5 + j], sxy);
        #pragma unroll
        for (int i = 0; i < 3; i++)
            #pragma unroll
            for (int j = 0; j < 3; j++)
                sxy = fmaf(win[(i+1)*5 + (j+1)], wk[i*3 + j], sxy);
        #pragma unroll
        for (int j = 0; j < 5; j++) sxz = fmaf(win[2*5 + j], wk[37+j], sxz);
        #pragma unroll
        for (int j = 0; j < 3; j++) sxz = fmaf(win[2*5 + j+1], wk[34+j], sxz);
        #pragma unroll
        for (int i = 0; i < 5; i++) syz = fmaf(win[i*5 + 2], wk[45+i], syz);
        #pragma unroll
        for (int i = 0; i < 3; i++) syz = fmaf(win[(i+1)*5 + 2], wk[42+i], syz);

        float fxy = fmaxf(fmaf(sxy, scxy, shxy), 0.f);
        float fxz = fmaxf(fmaf(sxz, scxz, shxz), 0.f);
        float fyz = fmaxf(fmaf(syz, scyz, shyz), 0.f);
        float z = al * fxz + be * fyz;
        float gate = 1.f / (1.f + expf(-z));
        g_top[base + p] = fmaxf(fxy * gate, 0.f);
    }
}

// ---------------------------------------------------------------------------
// K3: pw2 GEMM + BN + ReLU epilogue + SE squeeze partial sums.
__global__ __launch_bounds__(256) void k_pw2(
    const float* __restrict__ W,
    const float* __restrict__ bn2_g, const float* __restrict__ bn2_b,
    const float* __restrict__ bn2_m, const float* __restrict__ bn2_v) {
    const int b  = blockIdx.z;
    const int o0 = blockIdx.y * 128;
    const int p0 = blockIdx.x * 64;
    __shared__ float As[16][128];
    __shared__ float Bs[16][64];
    __shared__ float ssum[128];
    const int tid = threadIdx.x;
    const int tx = tid & 15, ty = tid >> 4;
    const float* Xb = g_top + (size_t)b * CC * PP;
    float acc[8][4] = {};
    if (tid < 128) ssum[tid] = 0.f;

    for (int kt = 0; kt < CC; kt += 16) {
        {
            int o  = o0 + (tid >> 1);
            int k4 = (tid & 1) * 8;
            const float4* src = reinterpret_cast<const float4*>(W + o * CC + kt + k4);
            float4 v0 = src[0], v1 = src[1];
            int col = tid >> 1;
            As[k4+0][col] = v0.x; As[k4+1][col] = v0.y;
            As[k4+2][col] = v0.z; As[k4+3][col] = v0.w;
            As[k4+4][col] = v1.x; As[k4+5][col] = v1.y;
            As[k4+6][col] = v1.z; As[k4+7][col] = v1.w;
        }
        {
            int k  = tid >> 4;
            int pp = (tid & 15) * 4;
            float4 v = *reinterpret_cast<const float4*>(Xb + (size_t)(kt + k) * PP + p0 + pp);
            *reinterpret_cast<float4*>(&Bs[k][pp]) = v;
        }
        __syncthreads();
        #pragma unroll
        for (int kk = 0; kk < 16; kk++) {
            float a[8], bb[4];
            *reinterpret_cast<float4*>(a)     = *reinterpret_cast<const float4*>(&As[kk][ty*8]);
            *reinterpret_cast<float4*>(a + 4) = *reinterpret_cast<const float4*>(&As[kk][ty*8+4]);
            *reinterpret_cast<float4*>(bb)    = *reinterpret_cast<const float4*>(&Bs[kk][tx*4]);
            #pragma unroll
            for (int i = 0; i < 8; i++)
                #pragma unroll
                for (int j = 0; j < 4; j++)
                    acc[i][j] = fmaf(a[i], bb[j], acc[i][j]);
        }
        __syncthreads();
    }
    #pragma unroll
    for (int i = 0; i < 8; i++) {
        int o = o0 + ty*8 + i;
        float sc = bn2_g[o] * rsqrtf(bn2_v[o] + EPSF);
        float sh = bn2_b[o] - bn2_m[o] * sc;
        float4 r;
        r.x = fmaxf(fmaf(acc[i][0], sc, sh), 0.f);
        r.y = fmaxf(fmaf(acc[i][1], sc, sh), 0.f);
        r.z = fmaxf(fmaf(acc[i][2], sc, sh), 0.f);
        r.w = fmaxf(fmaf(acc[i][3], sc, sh), 0.f);
        size_t off = (size_t)(b*CC + o) * PP + p0 + tx*4;
        *reinterpret_cast<float4*>(&g_out2[off]) = r;
        atomicAdd(&ssum[ty*8 + i], r.x + r.y + r.z + r.w);
    }
    __syncthreads();
    if (tid < 128) atomicAdd(&g_sum[b*CC + o0 + tid], ssum[tid]);
}

// ---------------------------------------------------------------------------
// K4: SE MLP per batch.  s -> relu(fc1) -> sigmoid(fc2)
__global__ __launch_bounds__(256) void k_se(
    const float* __restrict__ fc1_w, const float* __restrict__ fc1_b,
    const float* __restrict__ fc2_w, const float* __restrict__ fc2_b) {
    const int b = blockIdx.x;
    const int tid = threadIdx.x;
    __shared__ float s[CC];
    __shared__ float t[16];
    s[tid] = g_sum[b*CC + tid] * (1.f / (float)PP);
    __syncthreads();
    if (tid < 16) {
        float acc = fc1_b[tid];
        #pragma unroll 8
        for (int c = 0; c < CC; c++) acc = fmaf(fc1_w[tid*CC + c], s[c], acc);
        t[tid] = fmaxf(acc, 0.f);
    }
    __syncthreads();
    float acc = fc2_b[tid];
    #pragma unroll
    for (int m = 0; m < 16; m++) acc = fmaf(fc2_w[tid*16 + m], t[m], acc);
    g_se[b*CC + tid] = 1.f / (1.f + expf(-acc));
}

// ---------------------------------------------------------------------------
// K5: out = out2 * se[b,c] + x   (float4 elementwise)
__global__ __launch_bounds__(256) void k_final(const float* __restrict__ X,
                                               float* __restrict__ O) {
    int i4 = blockIdx.x * blockDim.x + threadIdx.x;   // NTOT/4 threads
    if (i4 >= NTOT/4) return;
    int i = i4 * 4;
    int bc = i / PP;               // == b*CC + c  (PP divides channel planes)
    float sf = g_se[bc];
    float4 o2 = *reinterpret_cast<const float4*>(&g_out2[i]);
    float4 xv = *reinterpret_cast<const float4*>(&X[i]);
    float4 r;
    r.x = fmaf(o2.x, sf, xv.x);
    r.y = fmaf(o2.y, sf, xv.y);
    r.z = fmaf(o2.z, sf, xv.z);
    r.w = fmaf(o2.w, sf, xv.w);
    *reinterpret_cast<float4*>(&O[i]) = r;
}

// ---------------------------------------------------------------------------
extern "C" void kernel_launch(void* const* d_in, const int* in_sizes, int n_in,
                              void* d_out, int out_size) {
    const float* x      = (const float*)d_in[0];
    const float* pw1_w  = (const float*)d_in[1];
    const float* xy3_w  = (const float*)d_in[2];
    const float* xy5_w  = (const float*)d_in[3];
    const float* bnxy_g = (const float*)d_in[4];
    const float* bnxy_b = (const float*)d_in[5];
    const float* bnxy_m = (const float*)d_in[6];
    const float* bnxy_v = (const float*)d_in[7];
    const float* xz3_w  = (const float*)d_in[8];
    const float* xz5_w  = (const float*)d_in[9];
    const float* bnxz_g = (const float*)d_in[10];
    const float* bnxz_b = (const float*)d_in[11];
    const float* bnxz_m = (const float*)d_in[12];
    const float* bnxz_v = (const float*)d_in[13];
    const float* yz3_w  = (const float*)d_in[14];
    const float* yz5_w  = (const float*)d_in[15];
    const float* bnyz_g = (const float*)d_in[16];
    const float* bnyz_b = (const float*)d_in[17];
    const float* bnyz_m = (const float*)d_in[18];
    const float* bnyz_v = (const float*)d_in[19];
    const float* alpha  = (const float*)d_in[20];
    const float* beta   = (const float*)d_in[21];
    const float* pw2_w  = (const float*)d_in[22];
    const float* bn2_g  = (const float*)d_in[23];
    const float* bn2_b  = (const float*)d_in[24];
    const float* bn2_m  = (const float*)d_in[25];
    const float* bn2_v  = (const float*)d_in[26];
    const float* fc1_w  = (const float*)d_in[27];
    const float* fc1_b  = (const float*)d_in[28];
    const float* fc2_w  = (const float*)d_in[29];
    const float* fc2_b  = (const float*)d_in[30];
    float* out = (float*)d_out;

    k_zero<<<16, 256>>>();
    k_pw1<<<dim3(49, 2, BB), 256>>>(x, pw1_w);
    k_dw<<<dim3(CC, BB), 256>>>(xy3_w, xy5_w, bnxy_g, bnxy_b, bnxy_m, bnxy_v,
                                xz3_w, xz5_w, bnxz_g, bnxz_b, bnxz_m, bnxz_v,
                                yz3_w, yz5_w, bnyz_g, bnyz_b, bnyz_m, bnyz_v,
                                alpha, beta);
    k_pw2<<<dim3(49, 2, BB), 256>>>(pw2_w, bn2_g, bn2_b, bn2_m, bn2_v);
    k_se<<<BB, 256>>>(fc1_w, fc1_b, fc2_w, fc2_b);
    k_final<<<(NTOT/4 + 255) / 256, 256>>>(x, out);
}

// round 3
// speedup vs baseline: 2.9966x; 2.9966x over previous
#include <cuda_runtime.h>
#include <cuda_bf16.h>
#include <math.h>
#include <stdint.h>

#define CC 256
#define HH 56
#define WW 56
#define PP (HH*WW)        // 3136
#define BB 16
#define NTOT (BB*CC*PP)
#define EPSF 1e-5f

// GEMM tiling
#define KT 32
#define AS_STRIDE 36              // floats per A smem row (32 + 4 pad)
#define BS_STRIDE 136             // floats per B smem row (128 + 8 pad)
#define AS_FLOATS (128*AS_STRIDE) // 4608
#define BS_FLOATS (KT*BS_STRIDE)  // 4352
#define STAGE_FLOATS (AS_FLOATS + BS_FLOATS)
#define GEMM_SMEM (2*STAGE_FLOATS*4)   // 71680 bytes

// Scratch
__device__ float g_mid[NTOT];    // pw1 out  [b][c][p]
__device__ float g_top[NTOT];    // dw out   [b][c][p]
__device__ float g_out2[NTOT];   // pw2 out  [b][c][p]
__device__ float g_sum[BB*CC];
__device__ float g_se[BB*CC];

// ---------------------------------------------------------------------------
__device__ __forceinline__ uint32_t s2u(const void* p) {
    uint32_t a;
    asm("{ .reg .u64 t; cvta.to.shared.u64 t, %1; cvt.u32.u64 %0, t; }"
        : "=r"(a) : "l"(p));
    return a;
}
__device__ __forceinline__ void cpa16(uint32_t dst, const float* src, bool pred) {
    asm volatile("cp.async.cg.shared.global [%0], [%1], 16, %2;"
                 :: "r"(dst), "l"(src), "r"(pred ? 16u : 0u));
}
#define CPA_COMMIT() asm volatile("cp.async.commit_group;" ::: "memory")

__device__ __forceinline__ void mma_tf32(float c[4], const uint32_t a[4],
                                         const uint32_t b[2]) {
    asm volatile(
        "mma.sync.aligned.m16n8k8.row.col.f32.tf32.tf32.f32 "
        "{%0,%1,%2,%3}, {%4,%5,%6,%7}, {%8,%9}, {%0,%1,%2,%3};"
        : "+f"(c[0]), "+f"(c[1]), "+f"(c[2]), "+f"(c[3])
        : "r"(a[0]), "r"(a[1]), "r"(a[2]), "r"(a[3]), "r"(b[0]), "r"(b[1]));
}

// ---------------------------------------------------------------------------
// GEMM mainloop: C[128 x 128] = A[128 x 256] * B[256 x 128]
// Ag: row-major, stride 256. Bg: row-major [k][p], stride PP. nvalid = PP-p0.
// Result in c[i][j][4]; warp (wm, wn), warp tile 64x32.
__device__ __forceinline__ void gemm_main(const float* __restrict__ Ag,
                                          const float* __restrict__ Bg,
                                          int nvalid, float c[4][4][4]) {
    extern __shared__ float sm[];
    const int tid  = threadIdx.x;
    const int lane = tid & 31;
    const int w    = tid >> 5;
    const int wm   = w >> 2, wn = w & 3;
    const uint32_t sbase = s2u(sm);

    // staging
    const int a_r  = tid >> 3, a_c4 = (tid & 7) * 4;       // +32 rows per iter
    const int b_r  = tid >> 5, b_c4 = (tid & 31) * 4;      // +8 rows per iter

    // fragment smem base offsets (bytes)
    const uint32_t a_frag0 = ((wm*64 + (lane >> 2)) * AS_STRIDE + (lane & 3)) * 4;
    const uint32_t b_frag0 = (AS_FLOATS + (lane & 3) * BS_STRIDE + wn*32 + (lane >> 2)) * 4;

    #pragma unroll
    for (int i = 0; i < 4; i++)
        #pragma unroll
        for (int j = 0; j < 4; j++)
            #pragma unroll
            for (int r = 0; r < 4; r++) c[i][j][r] = 0.f;

    // issue one stage's loads
    auto load_stage = [&](int kt, int stage) {
        uint32_t abase = sbase + (uint32_t)stage * STAGE_FLOATS * 4;
        uint32_t bbase = abase + AS_FLOATS * 4;
        #pragma unroll
        for (int it = 0; it < 4; it++) {
            int r = a_r + it * 32;
            cpa16(abase + (r * AS_STRIDE + a_c4) * 4,
                  Ag + (size_t)r * 256 + kt + a_c4, true);
        }
        #pragma unroll
        for (int it = 0; it < 4; it++) {
            int r = b_r + it * 8;
            cpa16(bbase + (r * BS_STRIDE + b_c4) * 4,
                  Bg + (size_t)(kt + r) * PP + b_c4, b_c4 < nvalid);
        }
        CPA_COMMIT();
    };

    load_stage(0, 0);
    load_stage(KT, 1);

    #pragma unroll 1
    for (int t = 0; t < 8; t++) {
        if (t < 7) asm volatile("cp.async.wait_group 1;" ::: "memory");
        else       asm volatile("cp.async.wait_group 0;" ::: "memory");
        __syncthreads();

        const uint32_t soff = (uint32_t)(t & 1) * STAGE_FLOATS * 4;
        const uint32_t ab = sbase + soff + a_frag0;
        const uint32_t bb = sbase + soff + b_frag0;
        #pragma unroll
        for (int k8 = 0; k8 < 4; k8++) {
            uint32_t a[4][4], bf[4][2];
            #pragma unroll
            for (int i = 0; i < 4; i++) {
                uint32_t base = ab + (i * 16 * AS_STRIDE + k8 * 8) * 4;
                asm volatile("ld.shared.b32 %0,[%1];" : "=r"(a[i][0]) : "r"(base));
                asm volatile("ld.shared.b32 %0,[%1];" : "=r"(a[i][1]) : "r"(base + 8*AS_STRIDE*4));
                asm volatile("ld.shared.b32 %0,[%1];" : "=r"(a[i][2]) : "r"(base + 16));
                asm volatile("ld.shared.b32 %0,[%1];" : "=r"(a[i][3]) : "r"(base + 8*AS_STRIDE*4 + 16));
            }
            #pragma unroll
            for (int j = 0; j < 4; j++) {
                uint32_t base = bb + (k8 * 8 * BS_STRIDE + j * 8) * 4;
                asm volatile("ld.shared.b32 %0,[%1];" : "=r"(bf[j][0]) : "r"(base));
                asm volatile("ld.shared.b32 %0,[%1];" : "=r"(bf[j][1]) : "r"(base + 4*BS_STRIDE*4));
            }
            #pragma unroll
            for (int i = 0; i < 4; i++)
                #pragma unroll
                for (int j = 0; j < 4; j++)
                    mma_tf32(c[i][j], a[i], bf[j]);
        }
        __syncthreads();
        if (t + 2 < 8) load_stage((t + 2) * KT, t & 1);
    }
}

// ---------------------------------------------------------------------------
// K1: pw1 GEMM -> g_mid
__global__ __launch_bounds__(256, 2) void k_pw1(const float* __restrict__ X,
                                                const float* __restrict__ W) {
    const int b  = blockIdx.z;
    const int o0 = blockIdx.y * 128;
    const int p0 = blockIdx.x * 128;
    const int lane = threadIdx.x & 31, w = threadIdx.x >> 5;
    const int wm = w >> 2, wn = w & 3;

    float c[4][4][4];
    gemm_main(W + (size_t)o0 * 256, X + (size_t)b * CC * PP + p0, PP - p0, c);

    float* dst = g_mid + (size_t)b * CC * PP;
    #pragma unroll
    for (int i = 0; i < 4; i++) {
        int o = o0 + wm*64 + i*16 + (lane >> 2);
        #pragma unroll
        for (int j = 0; j < 4; j++) {
            int pn = wn*32 + j*8 + (lane & 3)*2;
            if (p0 + pn < PP) {
                *reinterpret_cast<float2*>(dst + (size_t)o * PP + p0 + pn) =
                    make_float2(c[i][j][0], c[i][j][1]);
                *reinterpret_cast<float2*>(dst + (size_t)(o+8) * PP + p0 + pn) =
                    make_float2(c[i][j][2], c[i][j][3]);
            }
        }
    }
}

// ---------------------------------------------------------------------------
// K3: pw2 GEMM + BN + ReLU + SE squeeze -> g_out2, g_sum
__global__ __launch_bounds__(256, 2) void k_pw2(
    const float* __restrict__ W,
    const float* __restrict__ bn2_g, const float* __restrict__ bn2_b,
    const float* __restrict__ bn2_m, const float* __restrict__ bn2_v) {
    const int b  = blockIdx.z;
    const int o0 = blockIdx.y * 128;
    const int p0 = blockIdx.x * 128;
    const int lane = threadIdx.x & 31, w = threadIdx.x >> 5;
    const int wm = w >> 2, wn = w & 3;

    float c[4][4][4];
    gemm_main(W + (size_t)o0 * 256, g_top + (size_t)b * CC * PP + p0, PP - p0, c);

    float* dst = g_out2 + (size_t)b * CC * PP;
    #pragma unroll
    for (int i = 0; i < 4; i++) {
        int o = o0 + wm*64 + i*16 + (lane >> 2);
        float sc0 = bn2_g[o]   * rsqrtf(bn2_v[o]   + EPSF);
        float sh0 = bn2_b[o]   - bn2_m[o]   * sc0;
        float sc1 = bn2_g[o+8] * rsqrtf(bn2_v[o+8] + EPSF);
        float sh1 = bn2_b[o+8] - bn2_m[o+8] * sc1;
        float s0 = 0.f, s1 = 0.f;
        #pragma unroll
        for (int j = 0; j < 4; j++) {
            int pn = wn*32 + j*8 + (lane & 3)*2;
            if (p0 + pn < PP) {
                float v0 = fmaxf(fmaf(c[i][j][0], sc0, sh0), 0.f);
                float v1 = fmaxf(fmaf(c[i][j][1], sc0, sh0), 0.f);
                float v2 = fmaxf(fmaf(c[i][j][2], sc1, sh1), 0.f);
                float v3 = fmaxf(fmaf(c[i][j][3], sc1, sh1), 0.f);
                *reinterpret_cast<float2*>(dst + (size_t)o * PP + p0 + pn) =
                    make_float2(v0, v1);
                *reinterpret_cast<float2*>(dst + (size_t)(o+8) * PP + p0 + pn) =
                    make_float2(v2, v3);
                s0 += v0 + v1;
                s1 += v2 + v3;
            }
        }
        // reduce across the 4 lanes sharing this row (lane&3 varies)
        s0 += __shfl_xor_sync(0xFFFFFFFF, s0, 1);
        s0 += __shfl_xor_sync(0xFFFFFFFF, s0, 2);
        s1 += __shfl_xor_sync(0xFFFFFFFF, s1, 1);
        s1 += __shfl_xor_sync(0xFFFFFFFF, s1, 2);
        if ((lane & 3) == 0) {
            atomicAdd(&g_sum[b*CC + o],     s0);
            atomicAdd(&g_sum[b*CC + o + 8], s1);
        }
    }
}

// ---------------------------------------------------------------------------
// K0: zero SE accumulators
__global__ void k_zero() {
    int i = blockIdx.x * blockDim.x + threadIdx.x;
    if (i < BB*CC) g_sum[i] = 0.f;
}

// ---------------------------------------------------------------------------
// K2: fused depthwise branches + BN + ReLU + gate
__global__ __launch_bounds__(256) void k_dw(
    const float* __restrict__ xy3, const float* __restrict__ xy5,
    const float* __restrict__ bnxy_g, const float* __restrict__ bnxy_b,
    const float* __restrict__ bnxy_m, const float* __restrict__ bnxy_v,
    const float* __restrict__ xz3, const float* __restrict__ xz5,
    const float* __restrict__ bnxz_g, const float* __restrict__ bnxz_b,
    const float* __restrict__ bnxz_m, const float* __restrict__ bnxz_v,
    const float* __restrict__ yz3, const float* __restrict__ yz5,
    const float* __restrict__ bnyz_g, const float* __restrict__ bnyz_b,
    const float* __restrict__ bnyz_m, const float* __restrict__ bnyz_v,
    const float* __restrict__ alpha, const float* __restrict__ beta) {

    const int c = blockIdx.x;
    const int b = blockIdx.y;
    const int tid = threadIdx.x;
    const size_t base = (size_t)(b*CC + c) * PP;

    __shared__ float sp[60*60];
    __shared__ float wk[52];

    for (int idx = tid; idx < 60*60; idx += 256) {
        int r = idx / 60, cl = idx - r*60;
        int h = r - 2, w = cl - 2;
        float v = 0.f;
        if (h >= 0 && h < HH && w >= 0 && w < WW) v = g_mid[base + h*WW + w];
        sp[idx] = v;
    }
    if (tid < 9)       wk[tid] = xy3[c*9  + tid];
    else if (tid < 34) wk[tid] = xy5[c*25 + tid-9];
    else if (tid < 37) wk[tid] = xz3[c*3  + tid-34];
    else if (tid < 42) wk[tid] = xz5[c*5  + tid-37];
    else if (tid < 45) wk[tid] = yz3[c*3  + tid-42];
    else if (tid < 50) wk[tid] = yz5[c*5  + tid-45];
    __syncthreads();

    const float scxy = bnxy_g[c] * rsqrtf(bnxy_v[c] + EPSF);
    const float shxy = bnxy_b[c] - bnxy_m[c] * scxy;
    const float scxz = bnxz_g[c] * rsqrtf(bnxz_v[c] + EPSF);
    const float shxz = bnxz_b[c] - bnxz_m[c] * scxz;
    const float scyz = bnyz_g[c] * rsqrtf(bnyz_v[c] + EPSF);
    const float shyz = bnyz_b[c] - bnyz_m[c] * scyz;
    const float al = alpha[c], be = beta[c];

    for (int p = tid; p < PP; p += 256) {
        int hh = p / WW;
        int ww = p - hh*WW;
        float win[25];
        #pragma unroll
        for (int i = 0; i < 5; i++)
            #pragma unroll
            for (int j = 0; j < 5; j++)
                win[i*5+j] = sp[(hh+i)*60 + ww + j];

        float sxy = 0.f, sxz = 0.f, syz = 0.f;
        #pragma unroll
        for (int i = 0; i < 5; i++)
            #pragma unroll
            for (int j = 0; j < 5; j++)
                sxy = fmaf(win[i*5+j], wk[9 + i*5 + j], sxy);
        #pragma unroll
        for (int i = 0; i < 3; i++)
            #pragma unroll
            for (int j = 0; j < 3; j++)
                sxy = fmaf(win[(i+1)*5 + (j+1)], wk[i*3 + j], sxy);
        #pragma unroll
        for (int j = 0; j < 5; j++) sxz = fmaf(win[2*5 + j], wk[37+j], sxz);
        #pragma unroll
        for (int j = 0; j < 3; j++) sxz = fmaf(win[2*5 + j+1], wk[34+j], sxz);
        #pragma unroll
        for (int i = 0; i < 5; i++) syz = fmaf(win[i*5 + 2], wk[45+i], syz);
        #pragma unroll
        for (int i = 0; i < 3; i++) syz = fmaf(win[(i+1)*5 + 2], wk[42+i], syz);

        float fxy = fmaxf(fmaf(sxy, scxy, shxy), 0.f);
        float fxz = fmaxf(fmaf(sxz, scxz, shxz), 0.f);
        float fyz = fmaxf(fmaf(syz, scyz, shyz), 0.f);
        float z = al * fxz + be * fyz;
        float gate = 1.f / (1.f + expf(-z));
        g_top[base + p] = fmaxf(fxy * gate, 0.f);
    }
}

// ---------------------------------------------------------------------------
// K4: SE MLP per batch
__global__ __launch_bounds__(256) void k_se(
    const float* __restrict__ fc1_w, const float* __restrict__ fc1_b,
    const float* __restrict__ fc2_w, const float* __restrict__ fc2_b) {
    const int b = blockIdx.x;
    const int tid = threadIdx.x;
    __shared__ float s[CC];
    __shared__ float t[16];
    s[tid] = g_sum[b*CC + tid] * (1.f / (float)PP);
    __syncthreads();
    if (tid < 16) {
        float acc = fc1_b[tid];
        #pragma unroll 8
        for (int c = 0; c < CC; c++) acc = fmaf(fc1_w[tid*CC + c], s[c], acc);
        t[tid] = fmaxf(acc, 0.f);
    }
    __syncthreads();
    float acc = fc2_b[tid];
    #pragma unroll
    for (int m = 0; m < 16; m++) acc = fmaf(fc2_w[tid*16 + m], t[m], acc);
    g_se[b*CC + tid] = 1.f / (1.f + expf(-acc));
}

// ---------------------------------------------------------------------------
// K5: out = out2 * se[b,c] + x
__global__ __launch_bounds__(256) void k_final(const float* __restrict__ X,
                                               float* __restrict__ O) {
    int i4 = blockIdx.x * blockDim.x + threadIdx.x;
    if (i4 >= NTOT/4) return;
    int i = i4 * 4;
    int bc = i / PP;
    float sf = g_se[bc];
    float4 o2 = *reinterpret_cast<const float4*>(&g_out2[i]);
    float4 xv = *reinterpret_cast<const float4*>(&X[i]);
    float4 r;
    r.x = fmaf(o2.x, sf, xv.x);
    r.y = fmaf(o2.y, sf, xv.y);
    r.z = fmaf(o2.z, sf, xv.z);
    r.w = fmaf(o2.w, sf, xv.w);
    *reinterpret_cast<float4*>(&O[i]) = r;
}

// ---------------------------------------------------------------------------
extern "C" void kernel_launch(void* const* d_in, const int* in_sizes, int n_in,
                              void* d_out, int out_size) {
    const float* x      = (const float*)d_in[0];
    const float* pw1_w  = (const float*)d_in[1];
    const float* xy3_w  = (const float*)d_in[2];
    const float* xy5_w  = (const float*)d_in[3];
    const float* bnxy_g = (const float*)d_in[4];
    const float* bnxy_b = (const float*)d_in[5];
    const float* bnxy_m = (const float*)d_in[6];
    const float* bnxy_v = (const float*)d_in[7];
    const float* xz3_w  = (const float*)d_in[8];
    const float* xz5_w  = (const float*)d_in[9];
    const float* bnxz_g = (const float*)d_in[10];
    const float* bnxz_b = (const float*)d_in[11];
    const float* bnxz_m = (const float*)d_in[12];
    const float* bnxz_v = (const float*)d_in[13];
    const float* yz3_w  = (const float*)d_in[14];
    const float* yz5_w  = (const float*)d_in[15];
    const float* bnyz_g = (const float*)d_in[16];
    const float* bnyz_b = (const float*)d_in[17];
    const float* bnyz_m = (const float*)d_in[18];
    const float* bnyz_v = (const float*)d_in[19];
    const float* alpha  = (const float*)d_in[20];
    const float* beta   = (const float*)d_in[21];
    const float* pw2_w  = (const float*)d_in[22];
    const float* bn2_g  = (const float*)d_in[23];
    const float* bn2_b  = (const float*)d_in[24];
    const float* bn2_m  = (const float*)d_in[25];
    const float* bn2_v  = (const float*)d_in[26];
    const float* fc1_w  = (const float*)d_in[27];
    const float* fc1_b  = (const float*)d_in[28];
    const float* fc2_w  = (const float*)d_in[29];
    const float* fc2_b  = (const float*)d_in[30];
    float* out = (float*)d_out;

    static bool attr_done = false;
    if (!attr_done) {
        cudaFuncSetAttribute(k_pw1, cudaFuncAttributeMaxDynamicSharedMemorySize, GEMM_SMEM);
        cudaFuncSetAttribute(k_pw2, cudaFuncAttributeMaxDynamicSharedMemorySize, GEMM_SMEM);
        attr_done = true;
    }

    k_zero<<<16, 256>>>();
    k_pw1<<<dim3(25, 2, BB), 256, GEMM_SMEM>>>(x, pw1_w);
    k_dw<<<dim3(CC, BB), 256>>>(xy3_w, xy5_w, bnxy_g, bnxy_b, bnxy_m, bnxy_v,
                                xz3_w, xz5_w, bnxz_g, bnxz_b, bnxz_m, bnxz_v,
                                yz3_w, yz5_w, bnyz_g, bnyz_b, bnyz_m, bnyz_v,
                                alpha, beta);
    k_pw2<<<dim3(25, 2, BB), 256, GEMM_SMEM>>>(pw2_w, bn2_g, bn2_b, bn2_m, bn2_v);
    k_se<<<BB, 256>>>(fc1_w, fc1_b, fc2_w, fc2_b);
    k_final<<<(NTOT/4 + 255) / 256, 256>>>(x, out);
}

// round 4
// speedup vs baseline: 3.4966x; 1.1669x over previous
#include <cuda_runtime.h>
#include <cuda_bf16.h>
#include <math.h>
#include <stdint.h>

#define CC 256
#define HH 56
#define WW 56
#define PP (HH*WW)        // 3136
#define BB 16
#define NTOT (BB*CC*PP)
#define EPSF 1e-5f

// GEMM tiling (bf16, CTA 128x128, K-tile 32, 4-stage cp.async pipeline)
#define KT 32
#define A_STAGE_BYTES (128*64)        // 128 rows x 32 bf16 (64B)
#define B_STAGE_BYTES (32*256)        // 32 rows x 128 bf16 (256B)
#define STAGE_BYTES (A_STAGE_BYTES + B_STAGE_BYTES)   // 16384
#define NSTAGE 4
#define GEMM_SMEM (NSTAGE*STAGE_BYTES)                // 65536

// Scratch
__device__ __align__(16) float g_mid[NTOT];                 // pw1 out  [b][c][p] f32
__device__ __align__(16) __nv_bfloat16 g_xh[NTOT];          // x bf16   [b][c][p]
__device__ __align__(16) __nv_bfloat16 g_toph[NTOT];        // dw out   [b][c][p] bf16
__device__ __align__(16) float g_out2[NTOT];                // pw2 out  [b][c][p]
__device__ __align__(16) __nv_bfloat16 g_w1h[CC*CC];
__device__ __align__(16) __nv_bfloat16 g_w2h[CC*CC];
__device__ float g_sum[BB*CC];
__device__ float g_se[BB*CC];

// ---------------------------------------------------------------------------
__device__ __forceinline__ uint32_t s2u(const void* p) {
    uint32_t a;
    asm("{ .reg .u64 t; cvta.to.shared.u64 t, %1; cvt.u32.u64 %0, t; }"
        : "=r"(a) : "l"(p));
    return a;
}
__device__ __forceinline__ void cpa16(uint32_t dst, const void* src, bool pred) {
    asm volatile("cp.async.cg.shared.global [%0], [%1], 16, %2;"
                 :: "r"(dst), "l"(src), "r"(pred ? 16u : 0u));
}
#define CPA_COMMIT() asm volatile("cp.async.commit_group;" ::: "memory")

__device__ __forceinline__ void ldsm4(uint32_t& r0, uint32_t& r1, uint32_t& r2,
                                      uint32_t& r3, uint32_t addr) {
    asm volatile("ldmatrix.sync.aligned.m8n8.x4.shared.b16 {%0,%1,%2,%3}, [%4];"
                 : "=r"(r0), "=r"(r1), "=r"(r2), "=r"(r3) : "r"(addr));
}
__device__ __forceinline__ void ldsm4t(uint32_t& r0, uint32_t& r1, uint32_t& r2,
                                       uint32_t& r3, uint32_t addr) {
    asm volatile("ldmatrix.sync.aligned.m8n8.x4.trans.shared.b16 {%0,%1,%2,%3}, [%4];"
                 : "=r"(r0), "=r"(r1), "=r"(r2), "=r"(r3) : "r"(addr));
}
__device__ __forceinline__ void mma_bf16(float c[4], const uint32_t a[4],
                                         const uint32_t b[2]) {
    asm volatile(
        "mma.sync.aligned.m16n8k16.row.col.f32.bf16.bf16.f32 "
        "{%0,%1,%2,%3}, {%4,%5,%6,%7}, {%8,%9}, {%0,%1,%2,%3};"
        : "+f"(c[0]), "+f"(c[1]), "+f"(c[2]), "+f"(c[3])
        : "r"(a[0]), "r"(a[1]), "r"(a[2]), "r"(a[3]), "r"(b[0]), "r"(b[1]));
}

// ---------------------------------------------------------------------------
// GEMM mainloop: C[128 x 128] = A[128 x 256] * B[256 x 128]  (bf16 in, f32 acc)
// Ag: row-major stride 256 (bf16). Bg: [k][p] stride PP (bf16), pre-offset by p0.
__device__ __forceinline__ void gemm_main(const __nv_bfloat16* __restrict__ Ag,
                                          const __nv_bfloat16* __restrict__ Bg,
                                          int nvalid, float c[4][4][4]) {
    extern __shared__ char sm[];
    const int tid  = threadIdx.x;
    const int lane = tid & 31;
    const int w    = tid >> 5;
    const int wm   = w >> 2, wn = w & 3;
    const uint32_t sbase = s2u(sm);

    // ldmatrix lane geometry
    const int rowl = (lane & 7) + ((lane >> 3) & 1) * 8;
    const int hi   = lane >> 4;
    const int xa   = rowl & 3;      // A swizzle xor
    const int xb   = rowl & 7;      // B swizzle xor

    #pragma unroll
    for (int i = 0; i < 4; i++)
        #pragma unroll
        for (int j = 0; j < 4; j++)
            #pragma unroll
            for (int r = 0; r < 4; r++) c[i][j][r] = 0.f;

    // staging: 512 A chunks (m,c4) + 512 B chunks (k,c16); 2+2 per thread
    auto load_stage = [&](int t) {
        const int kt = t * KT;
        const uint32_t abase = sbase + (uint32_t)(t & (NSTAGE-1)) * STAGE_BYTES;
        const uint32_t bbase = abase + A_STAGE_BYTES;
        #pragma unroll
        for (int it = 0; it < 2; it++) {
            int q  = tid + it * 256;
            int m  = q >> 2, ch = q & 3;
            cpa16(abase + m*64 + ((ch ^ (m & 3)) << 4),
                  Ag + (size_t)m * 256 + kt + ch * 8, true);
        }
        #pragma unroll
        for (int it = 0; it < 2; it++) {
            int q  = tid + it * 256;
            int k  = q >> 4, ch = q & 15;
            cpa16(bbase + k*256 + ((ch ^ (k & 7)) << 4),
                  Bg + (size_t)(kt + k) * PP + ch * 8, ch * 8 < nvalid);
        }
        CPA_COMMIT();
    };

    load_stage(0); load_stage(1); load_stage(2);

    const uint32_t a_off = (uint32_t)((wm*64 + rowl) * 64);
    const uint32_t b_off = (uint32_t)(A_STAGE_BYTES + rowl * 256);

    #pragma unroll 1
    for (int t = 0; t < 8; t++) {
        __syncthreads();                      // close reads of stage (t-1)&3
        if (t + 3 < 8) load_stage(t + 3);
        else           CPA_COMMIT();          // empty group keeps wait count const
        asm volatile("cp.async.wait_group 3;" ::: "memory");
        __syncthreads();

        const uint32_t st = sbase + (uint32_t)(t & (NSTAGE-1)) * STAGE_BYTES;
        #pragma unroll
        for (int kk2 = 0; kk2 < 2; kk2++) {   // k16 groups within K-tile
            uint32_t a[4][4], bf[4][2];
            #pragma unroll
            for (int i = 0; i < 4; i++)
                ldsm4(a[i][0], a[i][1], a[i][2], a[i][3],
                      st + a_off + i*1024 + (((kk2*2 + hi) ^ xa) << 4));
            #pragma unroll
            for (int j2 = 0; j2 < 2; j2++)
                ldsm4t(bf[j2*2][0], bf[j2*2][1], bf[j2*2+1][0], bf[j2*2+1][1],
                       st + b_off + kk2*16*256 + (((wn*4 + j2*2 + hi) ^ xb) << 4));
            #pragma unroll
            for (int i = 0; i < 4; i++)
                #pragma unroll
                for (int j = 0; j < 4; j++)
                    mma_bf16(c[i][j], a[i], bf[j]);
        }
    }
}

// ---------------------------------------------------------------------------
// K1: pw1 GEMM -> g_mid (f32)
__global__ __launch_bounds__(256, 2) void k_pw1() {
    const int b  = blockIdx.z;
    const int o0 = blockIdx.y * 128;
    const int p0 = blockIdx.x * 128;
    const int lane = threadIdx.x & 31, w = threadIdx.x >> 5;
    const int wm = w >> 2, wn = w & 3;

    float c[4][4][4];
    gemm_main(g_w1h + (size_t)o0 * 256, g_xh + (size_t)b * CC * PP + p0, PP - p0, c);

    float* dst = g_mid + (size_t)b * CC * PP;
    #pragma unroll
    for (int i = 0; i < 4; i++) {
        int o = o0 + wm*64 + i*16 + (lane >> 2);
        #pragma unroll
        for (int j = 0; j < 4; j++) {
            int pn = wn*32 + j*8 + (lane & 3)*2;
            if (p0 + pn < PP) {
                *reinterpret_cast<float2*>(dst + (size_t)o * PP + p0 + pn) =
                    make_float2(c[i][j][0], c[i][j][1]);
                *reinterpret_cast<float2*>(dst + (size_t)(o+8) * PP + p0 + pn) =
                    make_float2(c[i][j][2], c[i][j][3]);
            }
        }
    }
}

// ---------------------------------------------------------------------------
// K3: pw2 GEMM + BN + ReLU + SE squeeze -> g_out2, g_sum
__global__ __launch_bounds__(256, 2) void k_pw2(
    const float* __restrict__ bn2_g, const float* __restrict__ bn2_b,
    const float* __restrict__ bn2_m, const float* __restrict__ bn2_v) {
    const int b  = blockIdx.z;
    const int o0 = blockIdx.y * 128;
    const int p0 = blockIdx.x * 128;
    const int lane = threadIdx.x & 31, w = threadIdx.x >> 5;
    const int wm = w >> 2, wn = w & 3;

    float c[4][4][4];
    gemm_main(g_w2h + (size_t)o0 * 256, g_toph + (size_t)b * CC * PP + p0, PP - p0, c);

    float* dst = g_out2 + (size_t)b * CC * PP;
    #pragma unroll
    for (int i = 0; i < 4; i++) {
        int o = o0 + wm*64 + i*16 + (lane >> 2);
        float sc0 = bn2_g[o]   * rsqrtf(bn2_v[o]   + EPSF);
        float sh0 = bn2_b[o]   - bn2_m[o]   * sc0;
        float sc1 = bn2_g[o+8] * rsqrtf(bn2_v[o+8] + EPSF);
        float sh1 = bn2_b[o+8] - bn2_m[o+8] * sc1;
        float s0 = 0.f, s1 = 0.f;
        #pragma unroll
        for (int j = 0; j < 4; j++) {
            int pn = wn*32 + j*8 + (lane & 3)*2;
            if (p0 + pn < PP) {
                float v0 = fmaxf(fmaf(c[i][j][0], sc0, sh0), 0.f);
                float v1 = fmaxf(fmaf(c[i][j][1], sc0, sh0), 0.f);
                float v2 = fmaxf(fmaf(c[i][j][2], sc1, sh1), 0.f);
                float v3 = fmaxf(fmaf(c[i][j][3], sc1, sh1), 0.f);
                *reinterpret_cast<float2*>(dst + (size_t)o * PP + p0 + pn) =
                    make_float2(v0, v1);
                *reinterpret_cast<float2*>(dst + (size_t)(o+8) * PP + p0 + pn) =
                    make_float2(v2, v3);
                s0 += v0 + v1;
                s1 += v2 + v3;
            }
        }
        s0 += __shfl_xor_sync(0xFFFFFFFF, s0, 1);
        s0 += __shfl_xor_sync(0xFFFFFFFF, s0, 2);
        s1 += __shfl_xor_sync(0xFFFFFFFF, s1, 1);
        s1 += __shfl_xor_sync(0xFFFFFFFF, s1, 2);
        if ((lane & 3) == 0) {
            atomicAdd(&g_sum[b*CC + o],     s0);
            atomicAdd(&g_sum[b*CC + o + 8], s1);
        }
    }
}

// ---------------------------------------------------------------------------
// K0: zero SE accumulators
__global__ void k_zero() {
    int i = blockIdx.x * blockDim.x + threadIdx.x;
    if (i < BB*CC) g_sum[i] = 0.f;
}

// Kc: convert x -> bf16 (8 elems/thread)
__global__ __launch_bounds__(256) void k_cvt(const float* __restrict__ X) {
    size_t i = ((size_t)blockIdx.x * 256 + threadIdx.x) * 8;
    if (i >= NTOT) return;
    float4 a = *reinterpret_cast<const float4*>(X + i);
    float4 b = *reinterpret_cast<const float4*>(X + i + 4);
    __nv_bfloat162 o[4];
    o[0] = __floats2bfloat162_rn(a.x, a.y);
    o[1] = __floats2bfloat162_rn(a.z, a.w);
    o[2] = __floats2bfloat162_rn(b.x, b.y);
    o[3] = __floats2bfloat162_rn(b.z, b.w);
    *reinterpret_cast<uint4*>(g_xh + i) = *reinterpret_cast<uint4*>(o);
}

// Kw: convert both weight matrices to bf16
__global__ __launch_bounds__(256) void k_cvtw(const float* __restrict__ W1,
                                              const float* __restrict__ W2) {
    int i = blockIdx.x * 256 + threadIdx.x;
    if (i < CC*CC) {
        g_w1h[i] = __float2bfloat16(W1[i]);
        g_w2h[i] = __float2bfloat16(W2[i]);
    }
}

// ---------------------------------------------------------------------------
// K2: fused depthwise branches + BN + ReLU + gate -> g_toph (bf16)
__global__ __launch_bounds__(256) void k_dw(
    const float* __restrict__ xy3, const float* __restrict__ xy5,
    const float* __restrict__ bnxy_g, const float* __restrict__ bnxy_b,
    const float* __restrict__ bnxy_m, const float* __restrict__ bnxy_v,
    const float* __restrict__ xz3, const float* __restrict__ xz5,
    const float* __restrict__ bnxz_g, const float* __restrict__ bnxz_b,
    const float* __restrict__ bnxz_m, const float* __restrict__ bnxz_v,
    const float* __restrict__ yz3, const float* __restrict__ yz5,
    const float* __restrict__ bnyz_g, const float* __restrict__ bnyz_b,
    const float* __restrict__ bnyz_m, const float* __restrict__ bnyz_v,
    const float* __restrict__ alpha, const float* __restrict__ beta) {

    const int c = blockIdx.x;
    const int b = blockIdx.y;
    const int tid = threadIdx.x;
    const size_t base = (size_t)(b*CC + c) * PP;

    __shared__ float sp[60*60];
    __shared__ float wk[52];

    for (int idx = tid; idx < 60*60; idx += 256) {
        int r = idx / 60, cl = idx - r*60;
        int h = r - 2, w = cl - 2;
        float v = 0.f;
        if (h >= 0 && h < HH && w >= 0 && w < WW) v = g_mid[base + h*WW + w];
        sp[idx] = v;
    }
    if (tid < 9)       wk[tid] = xy3[c*9  + tid];
    else if (tid < 34) wk[tid] = xy5[c*25 + tid-9];
    else if (tid < 37) wk[tid] = xz3[c*3  + tid-34];
    else if (tid < 42) wk[tid] = xz5[c*5  + tid-37];
    else if (tid < 45) wk[tid] = yz3[c*3  + tid-42];
    else if (tid < 50) wk[tid] = yz5[c*5  + tid-45];
    __syncthreads();

    const float scxy = bnxy_g[c] * rsqrtf(bnxy_v[c] + EPSF);
    const float shxy = bnxy_b[c] - bnxy_m[c] * scxy;
    const float scxz = bnxz_g[c] * rsqrtf(bnxz_v[c] + EPSF);
    const float shxz = bnxz_b[c] - bnxz_m[c] * scxz;
    const float scyz = bnyz_g[c] * rsqrtf(bnyz_v[c] + EPSF);
    const float shyz = bnyz_b[c] - bnyz_m[c] * scyz;
    const float al = alpha[c], be = beta[c];

    for (int p = tid; p < PP; p += 256) {
        int hh = p / WW;
        int ww = p - hh*WW;
        float win[25];
        #pragma unroll
        for (int i = 0; i < 5; i++)
            #pragma unroll
            for (int j = 0; j < 5; j++)
                win[i*5+j] = sp[(hh+i)*60 + ww + j];

        float sxy = 0.f, sxz = 0.f, syz = 0.f;
        #pragma unroll
        for (int i = 0; i < 5; i++)
            #pragma unroll
            for (int j = 0; j < 5; j++)
                sxy = fmaf(win[i*5+j], wk[9 + i*5 + j], sxy);
        #pragma unroll
        for (int i = 0; i < 3; i++)
            #pragma unroll
            for (int j = 0; j < 3; j++)
                sxy = fmaf(win[(i+1)*5 + (j+1)], wk[i*3 + j], sxy);
        #pragma unroll
        for (int j = 0; j < 5; j++) sxz = fmaf(win[2*5 + j], wk[37+j], sxz);
        #pragma unroll
        for (int j = 0; j < 3; j++) sxz = fmaf(win[2*5 + j+1], wk[34+j], sxz);
        #pragma unroll
        for (int i = 0; i < 5; i++) syz = fmaf(win[i*5 + 2], wk[45+i], syz);
        #pragma unroll
        for (int i = 0; i < 3; i++) syz = fmaf(win[(i+1)*5 + 2], wk[42+i], syz);

        float fxy = fmaxf(fmaf(sxy, scxy, shxy), 0.f);
        float fxz = fmaxf(fmaf(sxz, scxz, shxz), 0.f);
        float fyz = fmaxf(fmaf(syz, scyz, shyz), 0.f);
        float z = al * fxz + be * fyz;
        float gate = 1.f / (1.f + expf(-z));
        g_toph[base + p] = __float2bfloat16(fmaxf(fxy * gate, 0.f));
    }
}

// ---------------------------------------------------------------------------
// K4: SE MLP per batch
__global__ __launch_bounds__(256) void k_se(
    const float* __restrict__ fc1_w, const float* __restrict__ fc1_b,
    const float* __restrict__ fc2_w, const float* __restrict__ fc2_b) {
    const int b = blockIdx.x;
    const int tid = threadIdx.x;
    __shared__ float s[CC];
    __shared__ float t[16];
    s[tid] = g_sum[b*CC + tid] * (1.f / (float)PP);
    __syncthreads();
    if (tid < 16) {
        float acc = fc1_b[tid];
        #pragma unroll 8
        for (int c = 0; c < CC; c++) acc = fmaf(fc1_w[tid*CC + c], s[c], acc);
        t[tid] = fmaxf(acc, 0.f);
    }
    __syncthreads();
    float acc = fc2_b[tid];
    #pragma unroll
    for (int m = 0; m < 16; m++) acc = fmaf(fc2_w[tid*16 + m], t[m], acc);
    g_se[b*CC + tid] = 1.f / (1.f + expf(-acc));
}

// ---------------------------------------------------------------------------
// K5: out = out2 * se[b,c] + x
__global__ __launch_bounds__(256) void k_final(const float* __restrict__ X,
                                               float* __restrict__ O) {
    int i4 = blockIdx.x * blockDim.x + threadIdx.x;
    if (i4 >= NTOT/4) return;
    size_t i = (size_t)i4 * 4;
    int bc = (int)(i / PP);
    float sf = g_se[bc];
    float4 o2 = *reinterpret_cast<const float4*>(&g_out2[i]);
    float4 xv = *reinterpret_cast<const float4*>(&X[i]);
    float4 r;
    r.x = fmaf(o2.x, sf, xv.x);
    r.y = fmaf(o2.y, sf, xv.y);
    r.z = fmaf(o2.z, sf, xv.z);
    r.w = fmaf(o2.w, sf, xv.w);
    *reinterpret_cast<float4*>(&O[i]) = r;
}

// ---------------------------------------------------------------------------
extern "C" void kernel_launch(void* const* d_in, const int* in_sizes, int n_in,
                              void* d_out, int out_size) {
    const float* x      = (const float*)d_in[0];
    const float* pw1_w  = (const float*)d_in[1];
    const float* xy3_w  = (const float*)d_in[2];
    const float* xy5_w  = (const float*)d_in[3];
    const float* bnxy_g = (const float*)d_in[4];
    const float* bnxy_b = (const float*)d_in[5];
    const float* bnxy_m = (const float*)d_in[6];
    const float* bnxy_v = (const float*)d_in[7];
    const float* xz3_w  = (const float*)d_in[8];
    const float* xz5_w  = (const float*)d_in[9];
    const float* bnxz_g = (const float*)d_in[10];
    const float* bnxz_b = (const float*)d_in[11];
    const float* bnxz_m = (const float*)d_in[12];
    const float* bnxz_v = (const float*)d_in[13];
    const float* yz3_w  = (const float*)d_in[14];
    const float* yz5_w  = (const float*)d_in[15];
    const float* bnyz_g = (const float*)d_in[16];
    const float* bnyz_b = (const float*)d_in[17];
    const float* bnyz_m = (const float*)d_in[18];
    const float* bnyz_v = (const float*)d_in[19];
    const float* alpha  = (const float*)d_in[20];
    const float* beta   = (const float*)d_in[21];
    const float* pw2_w  = (const float*)d_in[22];
    const float* bn2_g  = (const float*)d_in[23];
    const float* bn2_b  = (const float*)d_in[24];
    const float* bn2_m  = (const float*)d_in[25];
    const float* bn2_v  = (const float*)d_in[26];
    const float* fc1_w  = (const float*)d_in[27];
    const float* fc1_b  = (const float*)d_in[28];
    const float* fc2_w  = (const float*)d_in[29];
    const float* fc2_b  = (const float*)d_in[30];
    float* out = (float*)d_out;

    static bool attr_done = false;
    if (!attr_done) {
        cudaFuncSetAttribute(k_pw1, cudaFuncAttributeMaxDynamicSharedMemorySize, GEMM_SMEM);
        cudaFuncSetAttribute(k_pw2, cudaFuncAttributeMaxDynamicSharedMemorySize, GEMM_SMEM);
        attr_done = true;
    }

    k_zero<<<16, 256>>>();
    k_cvtw<<<(CC*CC + 255)/256, 256>>>(pw1_w, pw2_w);
    k_cvt<<<(NTOT/8 + 255)/256, 256>>>(x);
    k_pw1<<<dim3(25, 2, BB), 256, GEMM_SMEM>>>();
    k_dw<<<dim3(CC, BB), 256>>>(xy3_w, xy5_w, bnxy_g, bnxy_b, bnxy_m, bnxy_v,
                                xz3_w, xz5_w, bnxz_g, bnxz_b, bnxz_m, bnxz_v,
                                yz3_w, yz5_w, bnyz_g, bnyz_b, bnyz_m, bnyz_v,
                                alpha, beta);
    k_pw2<<<dim3(25, 2, BB), 256, GEMM_SMEM>>>(bn2_g, bn2_b, bn2_m, bn2_v);
    k_se<<<BB, 256>>>(fc1_w, fc1_b, fc2_w, fc2_b);
    k_final<<<(NTOT/4 + 255) / 256, 256>>>(x, out);
}

// round 6
// speedup vs baseline: 4.1028x; 1.1733x over previous
#include <cuda_runtime.h>
#include <cuda_bf16.h>
#include <math.h>
#include <stdint.h>

#define CC 256
#define HH 56
#define WW 56
#define PP (HH*WW)        // 3136
#define BB 16
#define NTOT (BB*CC*PP)
#define EPSF 1e-5f

// GEMM tiling (bf16, CTA 128x128, K-tile 32, 4-stage cp.async pipeline)
#define KT 32
#define A_STAGE_BYTES (128*64)
#define B_STAGE_BYTES (32*256)
#define STAGE_BYTES (A_STAGE_BYTES + B_STAGE_BYTES)   // 16384
#define NSTAGE 4
#define GEMM_SMEM (NSTAGE*STAGE_BYTES)                // 65536

// Scratch
__device__ __align__(16) __nv_bfloat16 g_xh[NTOT];     // x bf16      [b][c][p]
__device__ __align__(16) __nv_bfloat16 g_midh[NTOT];   // pw1 out bf16
__device__ __align__(16) __nv_bfloat16 g_toph[NTOT];   // dw out bf16
__device__ __align__(16) float g_out2[NTOT];           // pw2 out f32
__device__ __align__(16) __nv_bfloat16 g_w1h[CC*CC];
__device__ __align__(16) __nv_bfloat16 g_w2h[CC*CC];
__device__ float g_sum[BB*CC];
__device__ float g_se[BB*CC];

// ---------------------------------------------------------------------------
__device__ __forceinline__ uint32_t s2u(const void* p) {
    uint32_t a;
    asm("{ .reg .u64 t; cvta.to.shared.u64 t, %1; cvt.u32.u64 %0, t; }"
        : "=r"(a) : "l"(p));
    return a;
}
__device__ __forceinline__ void cpa16(uint32_t dst, const void* src, bool pred) {
    asm volatile("cp.async.cg.shared.global [%0], [%1], 16, %2;"
                 :: "r"(dst), "l"(src), "r"(pred ? 16u : 0u));
}
#define CPA_COMMIT() asm volatile("cp.async.commit_group;" ::: "memory")

__device__ __forceinline__ void ldsm4(uint32_t& r0, uint32_t& r1, uint32_t& r2,
                                      uint32_t& r3, uint32_t addr) {
    asm volatile("ldmatrix.sync.aligned.m8n8.x4.shared.b16 {%0,%1,%2,%3}, [%4];"
                 : "=r"(r0), "=r"(r1), "=r"(r2), "=r"(r3) : "r"(addr));
}
__device__ __forceinline__ void ldsm4t(uint32_t& r0, uint32_t& r1, uint32_t& r2,
                                       uint32_t& r3, uint32_t addr) {
    asm volatile("ldmatrix.sync.aligned.m8n8.x4.trans.shared.b16 {%0,%1,%2,%3}, [%4];"
                 : "=r"(r0), "=r"(r1), "=r"(r2), "=r"(r3) : "r"(addr));
}
__device__ __forceinline__ void mma_bf16(float c[4], const uint32_t a[4],
                                         const uint32_t b[2]) {
    asm volatile(
        "mma.sync.aligned.m16n8k16.row.col.f32.bf16.bf16.f32 "
        "{%0,%1,%2,%3}, {%4,%5,%6,%7}, {%8,%9}, {%0,%1,%2,%3};"
        : "+f"(c[0]), "+f"(c[1]), "+f"(c[2]), "+f"(c[3])
        : "r"(a[0]), "r"(a[1]), "r"(a[2]), "r"(a[3]), "r"(b[0]), "r"(b[1]));
}

// ---------------------------------------------------------------------------
// GEMM mainloop: C[128 x 128] = A[128 x 256] * B[256 x 128]  (bf16 in, f32 acc)
__device__ __forceinline__ void gemm_main(const __nv_bfloat16* __restrict__ Ag,
                                          const __nv_bfloat16* __restrict__ Bg,
                                          int nvalid, float c[4][4][4]) {
    extern __shared__ char sm[];
    const int tid  = threadIdx.x;
    const int lane = tid & 31;
    const int w    = tid >> 5;
    const int wm   = w >> 2, wn = w & 3;
    const uint32_t sbase = s2u(sm);

    const int rowl = (lane & 7) + ((lane >> 3) & 1) * 8;
    const int hi   = lane >> 4;
    const int xa   = rowl & 3;
    const int xb   = rowl & 7;

    #pragma unroll
    for (int i = 0; i < 4; i++)
        #pragma unroll
        for (int j = 0; j < 4; j++)
            #pragma unroll
            for (int r = 0; r < 4; r++) c[i][j][r] = 0.f;

    auto load_stage = [&](int t) {
        const int kt = t * KT;
        const uint32_t abase = sbase + (uint32_t)(t & (NSTAGE-1)) * STAGE_BYTES;
        const uint32_t bbase = abase + A_STAGE_BYTES;
        #pragma unroll
        for (int it = 0; it < 2; it++) {
            int q  = tid + it * 256;
            int m  = q >> 2, ch = q & 3;
            cpa16(abase + m*64 + ((ch ^ (m & 3)) << 4),
                  Ag + (size_t)m * 256 + kt + ch * 8, true);
        }
        #pragma unroll
        for (int it = 0; it < 2; it++) {
            int q  = tid + it * 256;
            int k  = q >> 4, ch = q & 15;
            cpa16(bbase + k*256 + ((ch ^ (k & 7)) << 4),
                  Bg + (size_t)(kt + k) * PP + ch * 8, ch * 8 < nvalid);
        }
        CPA_COMMIT();
    };

    load_stage(0); load_stage(1); load_stage(2);

    const uint32_t a_off = (uint32_t)((wm*64 + rowl) * 64);
    const uint32_t b_off = (uint32_t)(A_STAGE_BYTES + rowl * 256);

    #pragma unroll 1
    for (int t = 0; t < 8; t++) {
        __syncthreads();
        if (t + 3 < 8) load_stage(t + 3);
        else           CPA_COMMIT();
        asm volatile("cp.async.wait_group 3;" ::: "memory");
        __syncthreads();

        const uint32_t st = sbase + (uint32_t)(t & (NSTAGE-1)) * STAGE_BYTES;
        #pragma unroll
        for (int kk2 = 0; kk2 < 2; kk2++) {
            uint32_t a[4][4], bf[4][2];
            #pragma unroll
            for (int i = 0; i < 4; i++)
                ldsm4(a[i][0], a[i][1], a[i][2], a[i][3],
                      st + a_off + i*1024 + (((kk2*2 + hi) ^ xa) << 4));
            #pragma unroll
            for (int j2 = 0; j2 < 2; j2++)
                ldsm4t(bf[j2*2][0], bf[j2*2][1], bf[j2*2+1][0], bf[j2*2+1][1],
                       st + b_off + kk2*16*256 + (((wn*4 + j2*2 + hi) ^ xb) << 4));
            #pragma unroll
            for (int i = 0; i < 4; i++)
                #pragma unroll
                for (int j = 0; j < 4; j++)
                    mma_bf16(c[i][j], a[i], bf[j]);
        }
    }
}

// ---------------------------------------------------------------------------
// K1: pw1 GEMM -> g_midh (bf16)
__global__ __launch_bounds__(256, 2) void k_pw1() {
    const int b  = blockIdx.z;
    const int o0 = blockIdx.y * 128;
    const int p0 = blockIdx.x * 128;
    const int lane = threadIdx.x & 31, w = threadIdx.x >> 5;
    const int wm = w >> 2, wn = w & 3;

    float c[4][4][4];
    gemm_main(g_w1h + (size_t)o0 * 256, g_xh + (size_t)b * CC * PP + p0, PP - p0, c);

    __nv_bfloat16* dst = g_midh + (size_t)b * CC * PP;
    #pragma unroll
    for (int i = 0; i < 4; i++) {
        int o = o0 + wm*64 + i*16 + (lane >> 2);
        #pragma unroll
        for (int j = 0; j < 4; j++) {
            int pn = wn*32 + j*8 + (lane & 3)*2;
            if (p0 + pn < PP) {
                *reinterpret_cast<__nv_bfloat162*>(dst + (size_t)o * PP + p0 + pn) =
                    __floats2bfloat162_rn(c[i][j][0], c[i][j][1]);
                *reinterpret_cast<__nv_bfloat162*>(dst + (size_t)(o+8) * PP + p0 + pn) =
                    __floats2bfloat162_rn(c[i][j][2], c[i][j][3]);
            }
        }
    }
}

// ---------------------------------------------------------------------------
// K3: pw2 GEMM + BN + ReLU + SE squeeze -> g_out2, g_sum
__global__ __launch_bounds__(256, 2) void k_pw2(
    const float* __restrict__ bn2_g, const float* __restrict__ bn2_b,
    const float* __restrict__ bn2_m, const float* __restrict__ bn2_v) {
    const int b  = blockIdx.z;
    const int o0 = blockIdx.y * 128;
    const int p0 = blockIdx.x * 128;
    const int lane = threadIdx.x & 31, w = threadIdx.x >> 5;
    const int wm = w >> 2, wn = w & 3;

    float c[4][4][4];
    gemm_main(g_w2h + (size_t)o0 * 256, g_toph + (size_t)b * CC * PP + p0, PP - p0, c);

    float* dst = g_out2 + (size_t)b * CC * PP;
    #pragma unroll
    for (int i = 0; i < 4; i++) {
        int o = o0 + wm*64 + i*16 + (lane >> 2);
        float sc0 = bn2_g[o]   * rsqrtf(bn2_v[o]   + EPSF);
        float sh0 = bn2_b[o]   - bn2_m[o]   * sc0;
        float sc1 = bn2_g[o+8] * rsqrtf(bn2_v[o+8] + EPSF);
        float sh1 = bn2_b[o+8] - bn2_m[o+8] * sc1;
        float s0 = 0.f, s1 = 0.f;
        #pragma unroll
        for (int j = 0; j < 4; j++) {
            int pn = wn*32 + j*8 + (lane & 3)*2;
            if (p0 + pn < PP) {
                float v0 = fmaxf(fmaf(c[i][j][0], sc0, sh0), 0.f);
                float v1 = fmaxf(fmaf(c[i][j][1], sc0, sh0), 0.f);
                float v2 = fmaxf(fmaf(c[i][j][2], sc1, sh1), 0.f);
                float v3 = fmaxf(fmaf(c[i][j][3], sc1, sh1), 0.f);
                *reinterpret_cast<float2*>(dst + (size_t)o * PP + p0 + pn) =
                    make_float2(v0, v1);
                *reinterpret_cast<float2*>(dst + (size_t)(o+8) * PP + p0 + pn) =
                    make_float2(v2, v3);
                s0 += v0 + v1;
                s1 += v2 + v3;
            }
        }
        s0 += __shfl_xor_sync(0xFFFFFFFF, s0, 1);
        s0 += __shfl_xor_sync(0xFFFFFFFF, s0, 2);
        s1 += __shfl_xor_sync(0xFFFFFFFF, s1, 1);
        s1 += __shfl_xor_sync(0xFFFFFFFF, s1, 2);
        if ((lane & 3) == 0) {
            atomicAdd(&g_sum[b*CC + o],     s0);
            atomicAdd(&g_sum[b*CC + o + 8], s1);
        }
    }
}

// ---------------------------------------------------------------------------
// K0: zero SE accumulators + convert weights (merged)
__global__ __launch_bounds__(256) void k_prep(const float* __restrict__ W1,
                                              const float* __restrict__ W2) {
    int i = blockIdx.x * 256 + threadIdx.x;
    if (i < CC*CC) {
        g_w1h[i] = __float2bfloat16(W1[i]);
        g_w2h[i] = __float2bfloat16(W2[i]);
    }
    if (i < BB*CC) g_sum[i] = 0.f;
}

// Kc: convert x -> bf16 (8 elems/thread)
__global__ __launch_bounds__(256) void k_cvt(const float* __restrict__ X) {
    size_t i = ((size_t)blockIdx.x * 256 + threadIdx.x) * 8;
    if (i >= NTOT) return;
    float4 a = *reinterpret_cast<const float4*>(X + i);
    float4 b = *reinterpret_cast<const float4*>(X + i + 4);
    __nv_bfloat162 o[4];
    o[0] = __floats2bfloat162_rn(a.x, a.y);
    o[1] = __floats2bfloat162_rn(a.z, a.w);
    o[2] = __floats2bfloat162_rn(b.x, b.y);
    o[3] = __floats2bfloat162_rn(b.z, b.w);
    *reinterpret_cast<uint4*>(g_xh + i) = *reinterpret_cast<uint4*>(o);
}

// ---------------------------------------------------------------------------
// K2: fused depthwise + BN + ReLU + gate. Sliding register window,
// pre-combined kernels, weights in registers. One block per (b,c) plane.
__global__ __launch_bounds__(256) void k_dw(
    const float* __restrict__ xy3, const float* __restrict__ xy5,
    const float* __restrict__ bnxy_g, const float* __restrict__ bnxy_b,
    const float* __restrict__ bnxy_m, const float* __restrict__ bnxy_v,
    const float* __restrict__ xz3, const float* __restrict__ xz5,
    const float* __restrict__ bnxz_g, const float* __restrict__ bnxz_b,
    const float* __restrict__ bnxz_m, const float* __restrict__ bnxz_v,
    const float* __restrict__ yz3, const float* __restrict__ yz5,
    const float* __restrict__ bnyz_g, const float* __restrict__ bnyz_b,
    const float* __restrict__ bnyz_m, const float* __restrict__ bnyz_v,
    const float* __restrict__ alpha, const float* __restrict__ beta) {

    const int c = blockIdx.x;
    const int b = blockIdx.y;
    const int tid = threadIdx.x;
    const size_t base = (size_t)(b*CC + c) * PP;

    __shared__ float sp[60*60];
    __shared__ float swe[36];

    // haloed plane from bf16 mid
    for (int idx = tid; idx < 3600; idx += 256) {
        int r = idx / 60, cl = idx - r*60;
        int h = r - 2, w = cl - 2;
        float v = 0.f;
        if (h >= 0 && h < HH && w >= 0 && w < WW)
            v = __bfloat162float(g_midh[base + h*WW + w]);
        sp[idx] = v;
    }
    // combined weights: [0..24]=xy (5x5+3x3), [25..29]=xz, [30..34]=yz
    if (tid < 25) {
        int i = tid / 5, j = tid - i*5;
        float v = xy5[c*25 + tid];
        if (i >= 1 && i <= 3 && j >= 1 && j <= 3) v += xy3[c*9 + (i-1)*3 + (j-1)];
        swe[tid] = v;
    } else if (tid < 30) {
        int j = tid - 25;
        float v = xz5[c*5 + j];
        if (j >= 1 && j <= 3) v += xz3[c*3 + j - 1];
        swe[tid] = v;
    } else if (tid < 35) {
        int i = tid - 30;
        float v = yz5[c*5 + i];
        if (i >= 1 && i <= 3) v += yz3[c*3 + i - 1];
        swe[tid] = v;
    }
    __syncthreads();

    if (tid >= 224) return;
    const int row = tid >> 2;              // 0..55
    const int seg = (tid & 3) * 14;        // 0,14,28,42

    const float scxy = bnxy_g[c] * rsqrtf(bnxy_v[c] + EPSF);
    const float shxy = bnxy_b[c] - bnxy_m[c] * scxy;
    const float scxz = bnxz_g[c] * rsqrtf(bnxz_v[c] + EPSF);
    const float shxz = bnxz_b[c] - bnxz_m[c] * scxz;
    const float scyz = bnyz_g[c] * rsqrtf(bnyz_v[c] + EPSF);
    const float shyz = bnyz_b[c] - bnyz_m[c] * scyz;
    const float al = alpha[c], be = beta[c];

    float we[25], wxz[5], wyz[5];
    #pragma unroll
    for (int i = 0; i < 25; i++) we[i] = swe[i];
    #pragma unroll
    for (int i = 0; i < 5; i++) { wxz[i] = swe[25+i]; wyz[i] = swe[30+i]; }

    // 5x5 register ring window over sp rows [row..row+4], cols [seg+s .. seg+s+4]
    float win[5][5];
    const float* spr = sp + row*60 + seg;
    #pragma unroll
    for (int i = 0; i < 5; i++)
        #pragma unroll
        for (int j = 0; j < 5; j++)
            win[i][j] = spr[i*60 + j];

    __nv_bfloat162 outbuf[7];
    #pragma unroll
    for (int s = 0; s < 14; s++) {
        float sxy = 0.f, sxz = 0.f, syz = 0.f;
        #pragma unroll
        for (int i = 0; i < 5; i++)
            #pragma unroll
            for (int j = 0; j < 5; j++)
                sxy = fmaf(win[i][(s+j) % 5], we[i*5+j], sxy);
        #pragma unroll
        for (int j = 0; j < 5; j++) sxz = fmaf(win[2][(s+j) % 5], wxz[j], sxz);
        #pragma unroll
        for (int i = 0; i < 5; i++) syz = fmaf(win[i][(s+2) % 5], wyz[i], syz);

        float fxy = fmaxf(fmaf(sxy, scxy, shxy), 0.f);
        float fxz = fmaxf(fmaf(sxz, scxz, shxz), 0.f);
        float fyz = fmaxf(fmaf(syz, scyz, shyz), 0.f);
        float z = fmaf(al, fxz, be * fyz);
        float gate = 1.f / (1.f + expf(-z));
        float r = fmaxf(fxy * gate, 0.f);
        __nv_bfloat16 h = __float2bfloat16(r);
        if (s & 1) outbuf[s >> 1].y = h;
        else       outbuf[s >> 1].x = h;

        if (s < 13) {
            #pragma unroll
            for (int i = 0; i < 5; i++)
                win[i][s % 5] = spr[i*60 + s + 5];
        }
    }
    __nv_bfloat16* dst = g_toph + base + row*WW + seg;
    #pragma unroll
    for (int s = 0; s < 7; s++)
        *reinterpret_cast<__nv_bfloat162*>(dst + 2*s) = outbuf[s];
}

// ---------------------------------------------------------------------------
// K4: SE MLP per batch
__global__ __launch_bounds__(256) void k_se(
    const float* __restrict__ fc1_w, const float* __restrict__ fc1_b,
    const float* __restrict__ fc2_w, const float* __restrict__ fc2_b) {
    const int b = blockIdx.x;
    const int tid = threadIdx.x;
    __shared__ float s[CC];
    __shared__ float t[16];
    s[tid] = g_sum[b*CC + tid] * (1.f / (float)PP);
    __syncthreads();
    if (tid < 16) {
        float acc = fc1_b[tid];
        #pragma unroll 8
        for (int c = 0; c < CC; c++) acc = fmaf(fc1_w[tid*CC + c], s[c], acc);
        t[tid] = fmaxf(acc, 0.f);
    }
    __syncthreads();
    float acc = fc2_b[tid];
    #pragma unroll
    for (int m = 0; m < 16; m++) acc = fmaf(fc2_w[tid*16 + m], t[m], acc);
    g_se[b*CC + tid] = 1.f / (1.f + expf(-acc));
}

// ---------------------------------------------------------------------------
// K5: out = out2 * se[b,c] + x
__global__ __launch_bounds__(256) void k_final(const float* __restrict__ X,
                                               float* __restrict__ O) {
    int i4 = blockIdx.x * blockDim.x + threadIdx.x;
    if (i4 >= NTOT/4) return;
    size_t i = (size_t)i4 * 4;
    int bc = (int)(i / PP);
    float sf = g_se[bc];
    float4 o2 = *reinterpret_cast<const float4*>(&g_out2[i]);
    float4 xv = *reinterpret_cast<const float4*>(&X[i]);
    float4 r;
    r.x = fmaf(o2.x, sf, xv.x);
    r.y = fmaf(o2.y, sf, xv.y);
    r.z = fmaf(o2.z, sf, xv.z);
    r.w = fmaf(o2.w, sf, xv.w);
    *reinterpret_cast<float4*>(&O[i]) = r;
}

// ---------------------------------------------------------------------------
extern "C" void kernel_launch(void* const* d_in, const int* in_sizes, int n_in,
                              void* d_out, int out_size) {
    const float* x      = (const float*)d_in[0];
    const float* pw1_w  = (const float*)d_in[1];
    const float* xy3_w  = (const float*)d_in[2];
    const float* xy5_w  = (const float*)d_in[3];
    const float* bnxy_g = (const float*)d_in[4];
    const float* bnxy_b = (const float*)d_in[5];
    const float* bnxy_m = (const float*)d_in[6];
    const float* bnxy_v = (const float*)d_in[7];
    const float* xz3_w  = (const float*)d_in[8];
    const float* xz5_w  = (const float*)d_in[9];
    const float* bnxz_g = (const float*)d_in[10];
    const float* bnxz_b = (const float*)d_in[11];
    const float* bnxz_m = (const float*)d_in[12];
    const float* bnxz_v = (const float*)d_in[13];
    const float* yz3_w  = (const float*)d_in[14];
    const float* yz5_w  = (const float*)d_in[15];
    const float* bnyz_g = (const float*)d_in[16];
    const float* bnyz_b = (const float*)d_in[17];
    const float* bnyz_m = (const float*)d_in[18];
    const float* bnyz_v = (const float*)d_in[19];
    const float* alpha  = (const float*)d_in[20];
    const float* beta   = (const float*)d_in[21];
    const float* pw2_w  = (const float*)d_in[22];
    const float* bn2_g  = (const float*)d_in[23];
    const float* bn2_b  = (const float*)d_in[24];
    const float* bn2_m  = (const float*)d_in[25];
    const float* bn2_v  = (const float*)d_in[26];
    const float* fc1_w  = (const float*)d_in[27];
    const float* fc1_b  = (const float*)d_in[28];
    const float* fc2_w  = (const float*)d_in[29];
    const float* fc2_b  = (const float*)d_in[30];
    float* out = (float*)d_out;

    static bool attr_done = false;
    if (!attr_done) {
        cudaFuncSetAttribute(k_pw1, cudaFuncAttributeMaxDynamicSharedMemorySize, GEMM_SMEM);
        cudaFuncSetAttribute(k_pw2, cudaFuncAttributeMaxDynamicSharedMemorySize, GEMM_SMEM);
        attr_done = true;
    }

    k_prep<<<(CC*CC + 255)/256, 256>>>(pw1_w, pw2_w);
    k_cvt<<<(NTOT/8 + 255)/256, 256>>>(x);
    k_pw1<<<dim3(25, 2, BB), 256, GEMM_SMEM>>>();
    k_dw<<<dim3(CC, BB), 256>>>(xy3_w, xy5_w, bnxy_g, bnxy_b, bnxy_m, bnxy_v,
                                xz3_w, xz5_w, bnxz_g, bnxz_b, bnxz_m, bnxz_v,
                                yz3_w, yz5_w, bnyz_g, bnyz_b, bnyz_m, bnyz_v,
                                alpha, beta);
    k_pw2<<<dim3(25, 2, BB), 256, GEMM_SMEM>>>(bn2_g, bn2_b, bn2_m, bn2_v);
    k_se<<<BB, 256>>>(fc1_w, fc1_b, fc2_w, fc2_b);
    k_final<<<(NTOT/4 + 255) / 256, 256>>>(x, out);
}